// round 9
// baseline (speedup 1.0000x reference)
#include <cuda_runtime.h>

typedef unsigned long long u64;

// ---- packed fp32x2 helpers (sm_103a FFMA2 path) ----
__device__ __forceinline__ void unpack2(u64 v, float& x, float& y) {
    asm("mov.b64 {%0, %1}, %2;" : "=f"(x), "=f"(y) : "l"(v));
}
__device__ __forceinline__ u64 ffma2(u64 a, u64 b, u64 c) {
    u64 d; asm("fma.rn.f32x2 %0, %1, %2, %3;" : "=l"(d) : "l"(a), "l"(b), "l"(c)); return d;
}
__device__ __forceinline__ float hadd2(u64 v) {
    float lo, hi; unpack2(v, lo, hi); return lo + hi;
}

// HW tanh (single MUFU op)
__device__ __forceinline__ float htanh(float x) {
    float y; asm("tanh.approx.f32 %0, %1;" : "=f"(y) : "f"(x)); return y;
}
__device__ __forceinline__ float hsig(float x) {
    return fmaf(0.5f, htanh(0.5f * x), 0.5f);   // 1 MUFU + 1 FMA
}

constexpr int S_LEN = 200;
constexpr int BINS  = 256;   // T steps
constexpr int H     = 64;
constexpr int ROWS  = 4;     // batch rows per CTA
constexpr int HSTR  = 72;    // hbuf row stride (floats): 288B == 32 mod 128 -> conflict-free
constexpr int HISTR = 260;   // hist row stride (floats): 1040B == 16 mod 128 -> conflict-free

// 256 threads, tid = u*4 + kq: u = tid>>2 (hidden unit), kq = tid&3 (k-quarter
// AND owned row). The 4 k-slices of unit u occupy 4 adjacent lanes, so the
// cross-slice gate reduction is a 2-stage warp butterfly (12 SHFL) instead of
// an SMEM exchange + extra barrier.
// XOR trick: accumulator slot a holds row r = a ^ kq, making butterfly
// register indices compile-time and leaving slot 0 = own row kq fully reduced.
// h is double-buffered -> ONE __syncthreads per step.
__global__ __launch_bounds__(256, 2)
void trend_lstm_kernel(const float* __restrict__ time_,
                       const int*   __restrict__ length_,
                       const float* __restrict__ predict_time_,
                       const float* __restrict__ W_ih,
                       const float* __restrict__ W_hh,
                       const float* __restrict__ b_ih,
                       const float* __restrict__ b_hh,
                       float* __restrict__ out)
{
    __shared__ alignas(16) float hist[ROWS * HISTR];
    __shared__ alignas(16) float hbuf[2][ROWS * HSTR];   // double-buffered h

    const int tid  = threadIdx.x;
    const int u    = tid >> 2;
    const int kq   = tid & 3;
    const int row0 = blockIdx.x * ROWS;

    // ---- init SMEM ----
    for (int i = tid; i < ROWS * HISTR; i += 256) hist[i] = 0.0f;
    for (int i = tid; i < 2 * ROWS * HSTR; i += 256) (&hbuf[0][0])[i] = 0.0f;
    __syncthreads();

    // ---- fused histogram: 64 threads (u) per row kq ----
    {
        const float pt  = predict_time_[row0 + kq];
        const int   len = length_[row0 + kq];
        const float* tr = time_ + (size_t)(row0 + kq) * S_LEN;
        for (int s = u; s < len; s += 64) {
            float tt  = tr[s];
            int   pos = (int)((pt - tt) * 0.25f);   // == /4.0f exactly; trunc
            if (pos >= 0 && pos < BINS)
                atomicAdd(&hist[kq * HISTR + (BINS - 1 - pos)], 1.0f);
        }
    }

    // ---- recurrent weights, packed over adjacent k (8B gmem loads) ----
    u64 w[4][8];
    const int kb = kq * 16;
#pragma unroll
    for (int g = 0; g < 4; g++) {
        const float* wr = W_hh + (size_t)(g * H + u) * H + kb;
#pragma unroll
        for (int p = 0; p < 8; p++)
            w[g][p] = *reinterpret_cast<const u64*>(wr + 2 * p);
    }
    float wih[4], bias[4];
#pragma unroll
    for (int g = 0; g < 4; g++) {
        wih[g]  = W_ih[g * H + u];
        bias[g] = b_ih[g * H + u] + b_hh[g * H + u];
    }

    float c = 0.0f, hout = 0.0f;
    __syncthreads();   // hist + hbuf[0] ready

    for (int t = 0; t < BINS; t++) {
        const float* hb  = hbuf[t & 1];
        float*       hbn = hbuf[(t & 1) ^ 1];

        float s[4][4];   // s[a][gate]: partial of row (a ^ kq), slice kq
#pragma unroll
        for (int a = 0; a < ROWS; a++) {
            const int r = a ^ kq;
            const ulonglong2* hp =
                reinterpret_cast<const ulonglong2*>(hb + r * HSTR + kb);
            u64 a0 = 0ull, a1 = 0ull, a2 = 0ull, a3 = 0ull;
#pragma unroll
            for (int q = 0; q < 4; q++) {
                ulonglong2 hh = hp[q];   // 16B, 4 distinct banks across kq groups
                a0 = ffma2(hh.x, w[0][2 * q], a0);
                a1 = ffma2(hh.x, w[1][2 * q], a1);
                a2 = ffma2(hh.x, w[2][2 * q], a2);
                a3 = ffma2(hh.x, w[3][2 * q], a3);
                a0 = ffma2(hh.y, w[0][2 * q + 1], a0);
                a1 = ffma2(hh.y, w[1][2 * q + 1], a1);
                a2 = ffma2(hh.y, w[2][2 * q + 1], a2);
                a3 = ffma2(hh.y, w[3][2 * q + 1], a3);
            }
            s[a][0] = hadd2(a0);
            s[a][1] = hadd2(a1);
            s[a][2] = hadd2(a2);
            s[a][3] = hadd2(a3);
        }

        // 2-stage butterfly over the 4 kq lanes of unit u (rows XOR-aligned)
#pragma unroll
        for (int g = 0; g < 4; g++) {
            s[0][g] += __shfl_xor_sync(0xFFFFFFFFu, s[1][g], 1);
            s[2][g] += __shfl_xor_sync(0xFFFFFFFFu, s[3][g], 1);
        }
#pragma unroll
        for (int g = 0; g < 4; g++)
            s[0][g] += __shfl_xor_sync(0xFFFFFFFFu, s[2][g], 2);

        // activation: thread owns (row kq, unit u)
        {
            float x  = hist[kq * HISTR + t];
            float gi = fmaf(x, wih[0], s[0][0] + bias[0]);
            float gf = fmaf(x, wih[1], s[0][1] + bias[1]);
            float gg = fmaf(x, wih[2], s[0][2] + bias[2]);
            float go = fmaf(x, wih[3], s[0][3] + bias[3]);

            float si = hsig(gi);
            float sf = hsig(gf);
            float tg = htanh(gg);
            float so = hsig(go);
            c    = sf * c + si * tg;
            hout = so * htanh(c);
            hbn[kq * HSTR + u] = hout;   // conflict-free (stride 288B)
        }
        __syncthreads();   // single barrier per step
    }

    out[(size_t)(row0 + kq) * H + u] = hout;
}

extern "C" void kernel_launch(void* const* d_in, const int* in_sizes, int n_in,
                              void* d_out, int out_size)
{
    const float* time_  = (const float*)d_in[0];   // [4096, 200]
    const int*   length = (const int*)  d_in[1];   // [4096]
    const float* ptime  = (const float*)d_in[2];   // [4096]
    const float* W_ih   = (const float*)d_in[3];   // [256, 1]
    const float* W_hh   = (const float*)d_in[4];   // [256, 64]
    const float* b_ih   = (const float*)d_in[5];   // [256]
    const float* b_hh   = (const float*)d_in[6];   // [256]
    float* out = (float*)d_out;                    // [4096, 64]

    const int B = in_sizes[1];                     // 4096 rows
    trend_lstm_kernel<<<B / ROWS, 256>>>(time_, length, ptime,
                                         W_ih, W_hh, b_ih, b_hh, out);
}

// round 11
// speedup vs baseline: 2.3524x; 2.3524x over previous
#include <cuda_runtime.h>
#include <cuda_fp16.h>

typedef unsigned int   u32;
typedef unsigned short u16;

// ======================= warp-MMA helpers (compute_80+, safe on compute_103) ==
__device__ __forceinline__ u32 smem_u32(const void* p) {
    u32 a;
    asm("{ .reg .u64 t; cvta.to.shared.u64 t, %1; cvt.u32.u64 %0, t; }"
        : "=r"(a) : "l"(p));
    return a;
}
__device__ __forceinline__ void ldsm4(u32* r, u32 addr) {
    asm volatile("ldmatrix.sync.aligned.m8n8.x4.shared.b16 {%0,%1,%2,%3}, [%4];"
                 : "=r"(r[0]), "=r"(r[1]), "=r"(r[2]), "=r"(r[3]) : "r"(addr));
}
__device__ __forceinline__ void mma16816(float* c, const u32* a, const u32* b) {
    asm volatile(
        "mma.sync.aligned.m16n8k16.row.col.f32.f16.f16.f32 "
        "{%0,%1,%2,%3}, {%4,%5,%6,%7}, {%8,%9}, {%0,%1,%2,%3};"
        : "+f"(c[0]), "+f"(c[1]), "+f"(c[2]), "+f"(c[3])
        : "r"(a[0]), "r"(a[1]), "r"(a[2]), "r"(a[3]), "r"(b[0]), "r"(b[1]));
}
__device__ __forceinline__ void sts16(u32 addr, u16 v) {
    asm volatile("st.shared.u16 [%0], %1;" :: "r"(addr), "h"(v) : "memory");
}
__device__ __forceinline__ void sts32(u32 addr, u32 v) {
    asm volatile("st.shared.u32 [%0], %1;" :: "r"(addr), "r"(v) : "memory");
}
__device__ __forceinline__ float htanh(float x) {
    float y; asm("tanh.approx.f32 %0, %1;" : "=f"(y) : "f"(x)); return y;
}
__device__ __forceinline__ float hsig(float x) { return fmaf(0.5f, htanh(0.5f * x), 0.5f); }

// ======================= constants =======================
constexpr int S_LEN = 200, BINS = 256, NR = 32;
// Row-major f16 tiles, row stride 304 bytes (mod 128 = 48 -> 8-row LDSM conflict-free)
// A: 256 rows; cols [0,64) W_hi, [64,128) W_lo, [128,132) epilogue (Wih_hi,Wih_lo,b_hi,b_lo)
// B: 32 rows;  cols [0,64) h_hi, [64,128) h_lo, [128..131] (x,x,1,1); double-buffered
constexpr int ASTR    = 304;                  // bytes per row
constexpr int OFF_B   = 256 * ASTR;           // 77824
constexpr int BBUF    = 32 * ASTR;            // 9728
constexpr int OFF_HS  = OFF_B + 2 * BBUF;     // 97280
constexpr int DYN_SMEM = OFF_HS + 32 * 257 * 4;  // 130176

// ======================= kernel =======================
// 256 threads = 8 warps. Warp w owns gate-rows [32w, 32w+32) == units 8w..8w+7.
// Row order inside a warp slab: j 0-7 = gate i of units, 8-15 = f, 16-23 = g,
// 24-31 = o  ==> thread T holds (i,f) of unit u=8w+T/4 in M-tile 2w accum rows
// (T/4, T/4+8) and (g,o) in M-tile 2w+1 -> activations fully in registers.
__global__ __launch_bounds__(256, 1)
void trend_lstm_mma(const float* __restrict__ time_,
                    const int*   __restrict__ length_,
                    const float* __restrict__ predict_time_,
                    const float* __restrict__ W_ih,
                    const float* __restrict__ W_hh,
                    const float* __restrict__ b_ih,
                    const float* __restrict__ b_hh,
                    float* __restrict__ out)
{
    extern __shared__ char sm[];
    float* hist = reinterpret_cast<float*>(sm + OFF_HS);    // [32][257]

    const int tid  = threadIdx.x;
    const int wid  = tid >> 5;
    const int lane = tid & 31;
    const int row0 = blockIdx.x * NR;
    const u32 Ab   = smem_u32(sm);
    const u32 Bb   = Ab + OFF_B;

    // ---- zero all SMEM ----
    for (int i = tid; i < DYN_SMEM / 4; i += 256)
        reinterpret_cast<u32*>(sm)[i] = 0u;
    __syncthreads();

    // ---- histogram (exact reference float math): 8 threads per batch row ----
    {
        const int r = tid & 31, sub = tid >> 5;
        const float pt  = predict_time_[row0 + r];
        const int   len = length_[row0 + r];
        const float* tr = time_ + (size_t)(row0 + r) * S_LEN;
        for (int s = sub; s < len; s += 8) {
            int pos = (int)((pt - tr[s]) * 0.25f);      // trunc toward 0, == /4
            if (pos >= 0 && pos < BINS)
                atomicAdd(&hist[r * 257 + (BINS - 1 - pos)], 1.0f);
        }
    }

    // ---- build A tile (f16 hi/lo splits of W_hh, reordered rows) ----
    for (int idx = tid; idx < 256 * 64; idx += 256) {
        int L = idx >> 6, k = idx & 63;
        int lw = L >> 5, j = L & 31;
        int unit = 8 * lw + (j & 7), gate = j >> 3;      // i,f,g,o order
        float wv = W_hh[(size_t)(gate * 64 + unit) * 64 + k];
        __half hi = __float2half_rn(wv);
        __half lo = __float2half_rn(wv - __half2float(hi));
        __half* Arow = reinterpret_cast<__half*>(sm + L * ASTR);
        Arow[k]      = hi;
        Arow[64 + k] = lo;
    }
    {   // epilogue chunk: x*W_ih + bias folded into K
        int L = tid, lw = L >> 5, j = L & 31;
        int unit = 8 * lw + (j & 7), gate = j >> 3;
        float wi = W_ih[gate * 64 + unit];
        float bb = b_ih[gate * 64 + unit] + b_hh[gate * 64 + unit];
        __half wh = __float2half_rn(wi), wl = __float2half_rn(wi - __half2float(wh));
        __half bh = __float2half_rn(bb), bl = __float2half_rn(bb - __half2float(bh));
        __half* Arow = reinterpret_cast<__half*>(sm + L * ASTR);
        Arow[128] = wh; Arow[129] = wl; Arow[130] = bh; Arow[131] = bl;
    }
    if (tid < 32) {     // B constants: (1,1) at cols 130,131 in BOTH buffers
        sts32(Bb + tid * ASTR + 260, 0x3C003C00u);
        sts32(Bb + BBUF + tid * ASTR + 260, 0x3C003C00u);
    }
    __syncthreads();

    if (tid < 32) {     // x(0) into buffer 0 (h0 = 0 already)
        u16 xh = __half_as_ushort(__float2half_rn(hist[tid * 257]));
        sts32(Bb + tid * ASTR + 256, (u32)xh | ((u32)xh << 16));
    }

    // ---- load static A fragments into registers (once) ----
    const int m  = lane >> 3, lr = lane & 7;
    u32 Ahi[4][2][4], Alo[4][2][4], Aep[2][4];
#pragma unroll
    for (int mt = 0; mt < 2; mt++) {
        int arow = 32 * wid + 16 * mt + 8 * (m & 1) + lr;
        u32 ab   = Ab + arow * ASTR + 16 * (m >> 1);
#pragma unroll
        for (int kt = 0; kt < 4; kt++) {
            ldsm4(Ahi[kt][mt], ab + 32 * kt);
            ldsm4(Alo[kt][mt], ab + 128 + 32 * kt);
        }
        ldsm4(Aep[mt], ab + 256);
    }

    const int u  = 8 * wid + (lane >> 2);    // owned unit
    const int bn = 8 * (m >> 1) + lr;        // B LDSM row within np-block
    const u32 bcol = 16 * (m & 1);
    float c_st[8], hl[8];
#pragma unroll
    for (int i = 0; i < 8; i++) c_st[i] = 0.0f;

    for (int t = 0; t < BINS; t++) {
        __syncthreads();                     // prev-step h writes visible
        const u32 Bcur = Bb + (t & 1) * BBUF;
        const u32 Bnxt = Bb + ((t & 1) ^ 1) * BBUF;

        float acc[2][4][4];
#pragma unroll
        for (int mt = 0; mt < 2; mt++)
#pragma unroll
            for (int nt = 0; nt < 4; nt++)
#pragma unroll
                for (int e = 0; e < 4; e++) acc[mt][nt][e] = 0.0f;

        const u32 ba0 = Bcur + bn * ASTR + bcol;
        const u32 ba1 = Bcur + (16 + bn) * ASTR + bcol;
#pragma unroll
        for (int kt = 0; kt < 9; kt++) {
            u32 br[8];                        // b-frags: nt0,nt1 (np0), nt2,nt3 (np1)
            ldsm4(br,     ba0 + 32 * kt);
            ldsm4(br + 4, ba1 + 32 * kt);
            if (kt < 4) {                     // W_hi x h_hi  AND  W_lo x h_hi (seg2 reuse)
#pragma unroll
                for (int mt = 0; mt < 2; mt++)
#pragma unroll
                    for (int nt = 0; nt < 4; nt++) {
                        mma16816(acc[mt][nt], Ahi[kt][mt], &br[2 * nt]);
                        mma16816(acc[mt][nt], Alo[kt][mt], &br[2 * nt]);
                    }
            } else if (kt < 8) {              // W_hi x h_lo
#pragma unroll
                for (int mt = 0; mt < 2; mt++)
#pragma unroll
                    for (int nt = 0; nt < 4; nt++)
                        mma16816(acc[mt][nt], Ahi[kt - 4][mt], &br[2 * nt]);
            } else {                          // epilogue: x*W_ih + b
#pragma unroll
                for (int mt = 0; mt < 2; mt++)
#pragma unroll
                    for (int nt = 0; nt < 4; nt++)
                        mma16816(acc[mt][nt], Aep[mt], &br[2 * nt]);
            }
        }

        // ---- activation: all 4 gates of unit u live in THIS thread's accums ----
#pragma unroll
        for (int nt = 0; nt < 4; nt++)
#pragma unroll
            for (int d = 0; d < 2; d++) {
                float gi = acc[0][nt][d],     gf = acc[0][nt][2 + d];
                float gg = acc[1][nt][d],     go = acc[1][nt][2 + d];
                int   ci = 2 * nt + d;
                float cc = hsig(gf) * c_st[ci] + hsig(gi) * htanh(gg);
                c_st[ci] = cc;
                float hv = hsig(go) * htanh(cc);
                hl[ci]   = hv;
                int cb = 8 * nt + 2 * (lane & 3) + d;     // local batch col
                __half hh = __float2half_rn(hv);
                __half lo = __float2half_rn(hv - __half2float(hh));
                u32 wa = Bnxt + cb * ASTR + 2 * u;
                sts16(wa,       __half_as_ushort(hh));
                sts16(wa + 128, __half_as_ushort(lo));
            }
        if (tid < 32) {                        // x(t+1)
            u16 xh = __half_as_ushort(__float2half_rn(hist[tid * 257 + t + 1]));
            sts32(Bnxt + tid * ASTR + 256, (u32)xh | ((u32)xh << 16));
        }
    }

#pragma unroll
    for (int nt = 0; nt < 4; nt++)
#pragma unroll
        for (int d = 0; d < 2; d++) {
            int cb = 8 * nt + 2 * (lane & 3) + d;
            out[(size_t)(row0 + cb) * 64 + u] = hl[2 * nt + d];
        }
}

extern "C" void kernel_launch(void* const* d_in, const int* in_sizes, int n_in,
                              void* d_out, int out_size)
{
    const float* time_  = (const float*)d_in[0];   // [4096, 200]
    const int*   length = (const int*)  d_in[1];   // [4096]
    const float* ptime  = (const float*)d_in[2];   // [4096]
    const float* W_ih   = (const float*)d_in[3];   // [256, 1]
    const float* W_hh   = (const float*)d_in[4];   // [256, 64]
    const float* b_ih   = (const float*)d_in[5];   // [256]
    const float* b_hh   = (const float*)d_in[6];   // [256]
    float* out = (float*)d_out;                    // [4096, 64]

    cudaFuncSetAttribute(trend_lstm_mma,
                         cudaFuncAttributeMaxDynamicSharedMemorySize, DYN_SMEM);
    const int B = in_sizes[1];                     // 4096
    trend_lstm_mma<<<B / NR, 256, DYN_SMEM>>>(time_, length, ptime,
                                              W_ih, W_hh, b_ih, b_hh, out);
}

// round 13
// speedup vs baseline: 2.5406x; 1.0800x over previous
#include <cuda_runtime.h>
#include <cuda_fp16.h>

typedef unsigned int   u32;
typedef unsigned short u16;

// ======================= warp-MMA helpers (compute_80+, safe on compute_103) ==
__device__ __forceinline__ u32 smem_u32(const void* p) {
    u32 a;
    asm("{ .reg .u64 t; cvta.to.shared.u64 t, %1; cvt.u32.u64 %0, t; }"
        : "=r"(a) : "l"(p));
    return a;
}
__device__ __forceinline__ void ldsm4(u32* r, u32 addr) {
    asm volatile("ldmatrix.sync.aligned.m8n8.x4.shared.b16 {%0,%1,%2,%3}, [%4];"
                 : "=r"(r[0]), "=r"(r[1]), "=r"(r[2]), "=r"(r[3]) : "r"(addr));
}
__device__ __forceinline__ void mma16816(float* c, const u32* a, const u32* b) {
    asm volatile(
        "mma.sync.aligned.m16n8k16.row.col.f32.f16.f16.f32 "
        "{%0,%1,%2,%3}, {%4,%5,%6,%7}, {%8,%9}, {%0,%1,%2,%3};"
        : "+f"(c[0]), "+f"(c[1]), "+f"(c[2]), "+f"(c[3])
        : "r"(a[0]), "r"(a[1]), "r"(a[2]), "r"(a[3]), "r"(b[0]), "r"(b[1]));
}
__device__ __forceinline__ void sts16(u32 addr, u16 v) {
    asm volatile("st.shared.u16 [%0], %1;" :: "r"(addr), "h"(v) : "memory");
}
__device__ __forceinline__ void sts32(u32 addr, u32 v) {
    asm volatile("st.shared.u32 [%0], %1;" :: "r"(addr), "r"(v) : "memory");
}
__device__ __forceinline__ float htanh(float x) {
    float y; asm("tanh.approx.f32 %0, %1;" : "=f"(y) : "f"(x)); return y;
}
__device__ __forceinline__ float hsig(float x) { return fmaf(0.5f, htanh(0.5f * x), 0.5f); }

// ======================= constants =======================
constexpr int S_LEN = 200, BINS = 256, NR = 16;   // 16 batch rows per CTA -> 2 CTAs/SM
// Row-major f16 tiles, row stride 304 bytes (mod 128 = 48 -> 8-row LDSM conflict-free)
// A: 256 rows; cols [0,64) W_hi, [64,128) W_lo, [128,132) epilogue (Wih_hi,Wih_lo,b_hi,b_lo)
// B: 16 rows;  cols [0,64) h_hi, [64,128) h_lo, [128..131] (x,x,1,1); double-buffered
constexpr int ASTR     = 304;                     // bytes per row
constexpr int OFF_B    = 256 * ASTR;              // 77824
constexpr int BBUF     = NR * ASTR;               // 4864
constexpr int OFF_HS   = OFF_B + 2 * BBUF;        // 87552
constexpr int DYN_SMEM = OFF_HS + NR * 257 * 4;   // 103984

// ======================= kernel =======================
// 256 threads = 8 warps, 2 CTAs/SM. Warp w owns gate-rows [32w, 32w+32) ==
// units 8w..8w+7 (row order: j 0-7 = gate i, 8-15 = f, 16-23 = g, 24-31 = o).
// Thread T holds (i,f) of unit u=8w+T/4 in M-tile 2w accum rows (T/4, T/4+8)
// and (g,o) in M-tile 2w+1 -> all 4 gates in-register, zero epilogue exchange.
__global__ __launch_bounds__(256, 2)
void trend_lstm_mma(const float* __restrict__ time_,
                    const int*   __restrict__ length_,
                    const float* __restrict__ predict_time_,
                    const float* __restrict__ W_ih,
                    const float* __restrict__ W_hh,
                    const float* __restrict__ b_ih,
                    const float* __restrict__ b_hh,
                    float* __restrict__ out)
{
    extern __shared__ char sm[];
    float* hist = reinterpret_cast<float*>(sm + OFF_HS);    // [16][257]

    const int tid  = threadIdx.x;
    const int wid  = tid >> 5;
    const int lane = tid & 31;
    const int row0 = blockIdx.x * NR;
    const u32 Ab   = smem_u32(sm);
    const u32 Bb   = Ab + OFF_B;

    // ---- zero all SMEM ----
    for (int i = tid; i < DYN_SMEM / 4; i += 256)
        reinterpret_cast<u32*>(sm)[i] = 0u;
    __syncthreads();

    // ---- histogram (exact reference float math): 16 threads per batch row ----
    {
        const int r = tid & 15, sub = tid >> 4;
        const float pt  = predict_time_[row0 + r];
        const int   len = length_[row0 + r];
        const float* tr = time_ + (size_t)(row0 + r) * S_LEN;
        for (int s = sub; s < len; s += 16) {
            int pos = (int)((pt - tr[s]) * 0.25f);      // trunc toward 0, == /4
            if (pos >= 0 && pos < BINS)
                atomicAdd(&hist[r * 257 + (BINS - 1 - pos)], 1.0f);
        }
    }

    // ---- build A tile (f16 hi/lo splits of W_hh, reordered rows) ----
    for (int idx = tid; idx < 256 * 64; idx += 256) {
        int L = idx >> 6, k = idx & 63;
        int lw = L >> 5, j = L & 31;
        int unit = 8 * lw + (j & 7), gate = j >> 3;      // i,f,g,o order
        float wv = W_hh[(size_t)(gate * 64 + unit) * 64 + k];
        __half hi = __float2half_rn(wv);
        __half lo = __float2half_rn(wv - __half2float(hi));
        __half* Arow = reinterpret_cast<__half*>(sm + L * ASTR);
        Arow[k]      = hi;
        Arow[64 + k] = lo;
    }
    {   // epilogue chunk: x*W_ih + bias folded into K
        int L = tid, lw = L >> 5, j = L & 31;
        int unit = 8 * lw + (j & 7), gate = j >> 3;
        float wi = W_ih[gate * 64 + unit];
        float bb = b_ih[gate * 64 + unit] + b_hh[gate * 64 + unit];
        __half wh = __float2half_rn(wi), wl = __float2half_rn(wi - __half2float(wh));
        __half bh = __float2half_rn(bb), bl = __float2half_rn(bb - __half2float(bh));
        __half* Arow = reinterpret_cast<__half*>(sm + L * ASTR);
        Arow[128] = wh; Arow[129] = wl; Arow[130] = bh; Arow[131] = bl;
    }
    if (tid < NR) {     // B constants: (1,1) at cols 130,131 in BOTH buffers
        sts32(Bb + tid * ASTR + 260, 0x3C003C00u);
        sts32(Bb + BBUF + tid * ASTR + 260, 0x3C003C00u);
    }
    __syncthreads();

    if (tid < NR) {     // x(0) into buffer 0 (h0 = 0 already)
        u16 xh = __half_as_ushort(__float2half_rn(hist[tid * 257]));
        sts32(Bb + tid * ASTR + 256, (u32)xh | ((u32)xh << 16));
    }

    // ---- load static A fragments into registers (once) ----
    const int m  = lane >> 3, lr = lane & 7;
    u32 Ahi[4][2][4], Alo[4][2][4], Aep[2][4];
#pragma unroll
    for (int mt = 0; mt < 2; mt++) {
        int arow = 32 * wid + 16 * mt + 8 * (m & 1) + lr;
        u32 ab   = Ab + arow * ASTR + 16 * (m >> 1);
#pragma unroll
        for (int kt = 0; kt < 4; kt++) {
            ldsm4(Ahi[kt][mt], ab + 32 * kt);
            ldsm4(Alo[kt][mt], ab + 128 + 32 * kt);
        }
        ldsm4(Aep[mt], ab + 256);
    }

    const int u = 8 * wid + (lane >> 2);     // owned unit
    // B LDSM: one x4 per kt covers all 16 batch rows x 16 k
    const u32 bfa = Bb + (8 * (m >> 1) + lr) * ASTR + 16 * (m & 1);
    float c_st[4], hl[4];
#pragma unroll
    for (int i = 0; i < 4; i++) c_st[i] = 0.0f;

    for (int t = 0; t < BINS; t++) {
        __syncthreads();                     // prev-step h writes visible
        const u32 bcur = bfa + (t & 1) * BBUF;
        const u32 Bnxt = Bb + ((t & 1) ^ 1) * BBUF;

        float acc[2][2][4];
#pragma unroll
        for (int mt = 0; mt < 2; mt++)
#pragma unroll
            for (int nt = 0; nt < 2; nt++)
#pragma unroll
                for (int e = 0; e < 4; e++) acc[mt][nt][e] = 0.0f;

#pragma unroll
        for (int kt = 0; kt < 9; kt++) {
            u32 br[4];                        // frags for nt0 (n0-7) + nt1 (n8-15)
            ldsm4(br, bcur + 32 * kt);
            if (kt < 4) {                     // W_hi x h_hi  AND  W_lo x h_hi
#pragma unroll
                for (int mt = 0; mt < 2; mt++)
#pragma unroll
                    for (int nt = 0; nt < 2; nt++) {
                        mma16816(acc[mt][nt], Ahi[kt][mt], &br[2 * nt]);
                        mma16816(acc[mt][nt], Alo[kt][mt], &br[2 * nt]);
                    }
            } else if (kt < 8) {              // W_hi x h_lo
#pragma unroll
                for (int mt = 0; mt < 2; mt++)
#pragma unroll
                    for (int nt = 0; nt < 2; nt++)
                        mma16816(acc[mt][nt], Ahi[kt - 4][mt], &br[2 * nt]);
            } else {                          // epilogue: x*W_ih + b
#pragma unroll
                for (int mt = 0; mt < 2; mt++)
#pragma unroll
                    for (int nt = 0; nt < 2; nt++)
                        mma16816(acc[mt][nt], Aep[mt], &br[2 * nt]);
            }
        }

        // ---- activation: all 4 gates of unit u live in THIS thread's accums ----
#pragma unroll
        for (int nt = 0; nt < 2; nt++)
#pragma unroll
            for (int d = 0; d < 2; d++) {
                float gi = acc[0][nt][d],     gf = acc[0][nt][2 + d];
                float gg = acc[1][nt][d],     go = acc[1][nt][2 + d];
                int   ci = 2 * nt + d;
                float cc = hsig(gf) * c_st[ci] + hsig(gi) * htanh(gg);
                c_st[ci] = cc;
                float hv = hsig(go) * htanh(cc);
                hl[ci]   = hv;
                int cb = 8 * nt + 2 * (lane & 3) + d;     // local batch col 0-15
                __half hh = __float2half_rn(hv);
                __half lo = __float2half_rn(hv - __half2float(hh));
                u32 wa = Bnxt + cb * ASTR + 2 * u;
                sts16(wa,       __half_as_ushort(hh));
                sts16(wa + 128, __half_as_ushort(lo));
            }
        if (tid < NR) {                        // x(t+1)
            u16 xh = __half_as_ushort(__float2half_rn(hist[tid * 257 + t + 1]));
            sts32(Bnxt + tid * ASTR + 256, (u32)xh | ((u32)xh << 16));
        }
    }

#pragma unroll
    for (int nt = 0; nt < 2; nt++)
#pragma unroll
        for (int d = 0; d < 2; d++) {
            int cb = 8 * nt + 2 * (lane & 3) + d;
            out[(size_t)(row0 + cb) * 64 + u] = hl[2 * nt + d];
        }
}

extern "C" void kernel_launch(void* const* d_in, const int* in_sizes, int n_in,
                              void* d_out, int out_size)
{
    const float* time_  = (const float*)d_in[0];   // [4096, 200]
    const int*   length = (const int*)  d_in[1];   // [4096]
    const float* ptime  = (const float*)d_in[2];   // [4096]
    const float* W_ih   = (const float*)d_in[3];   // [256, 1]
    const float* W_hh   = (const float*)d_in[4];   // [256, 64]
    const float* b_ih   = (const float*)d_in[5];   // [256]
    const float* b_hh   = (const float*)d_in[6];   // [256]
    float* out = (float*)d_out;                    // [4096, 64]

    cudaFuncSetAttribute(trend_lstm_mma,
                         cudaFuncAttributeMaxDynamicSharedMemorySize, DYN_SMEM);
    const int B = in_sizes[1];                     // 4096
    trend_lstm_mma<<<B / NR, 256, DYN_SMEM>>>(time_, length, ptime,
                                              W_ih, W_hh, b_ih, b_hh, out);
}

// round 14
// speedup vs baseline: 3.1876x; 1.2547x over previous
#include <cuda_runtime.h>
#include <cuda_fp16.h>

typedef unsigned int   u32;
typedef unsigned short u16;

// ======================= warp-MMA helpers (compute_80+, safe on compute_103) ==
__device__ __forceinline__ u32 smem_u32(const void* p) {
    u32 a;
    asm("{ .reg .u64 t; cvta.to.shared.u64 t, %1; cvt.u32.u64 %0, t; }"
        : "=r"(a) : "l"(p));
    return a;
}
__device__ __forceinline__ void ldsm4(u32* r, u32 addr) {
    asm volatile("ldmatrix.sync.aligned.m8n8.x4.shared.b16 {%0,%1,%2,%3}, [%4];"
                 : "=r"(r[0]), "=r"(r[1]), "=r"(r[2]), "=r"(r[3]) : "r"(addr));
}
__device__ __forceinline__ void mma16816(float* c, const u32* a, const u32* b) {
    asm volatile(
        "mma.sync.aligned.m16n8k16.row.col.f32.f16.f16.f32 "
        "{%0,%1,%2,%3}, {%4,%5,%6,%7}, {%8,%9}, {%0,%1,%2,%3};"
        : "+f"(c[0]), "+f"(c[1]), "+f"(c[2]), "+f"(c[3])
        : "r"(a[0]), "r"(a[1]), "r"(a[2]), "r"(a[3]), "r"(b[0]), "r"(b[1]));
}
__device__ __forceinline__ void sts16(u32 addr, u16 v) {
    asm volatile("st.shared.u16 [%0], %1;" :: "r"(addr), "h"(v) : "memory");
}
__device__ __forceinline__ void sts32(u32 addr, u32 v) {
    asm volatile("st.shared.u32 [%0], %1;" :: "r"(addr), "r"(v) : "memory");
}
__device__ __forceinline__ float htanh(float x) {
    float y; asm("tanh.approx.f32 %0, %1;" : "=f"(y) : "f"(x)); return y;
}
__device__ __forceinline__ float hsig(float x) { return fmaf(0.5f, htanh(0.5f * x), 0.5f); }

// ======================= constants =======================
constexpr int S_LEN = 200, BINS = 256, NR = 16;   // 16 batch rows/CTA -> 2 CTAs/SM
// Row-major f16 tiles, row stride 304 bytes (mod 128 = 48 -> 8-row LDSM conflict-free)
// A: 256 rows; cols [0,64) W_hi, [64,128) unused, [128,132) epilogue
//    (Wih_hi, Wih_lo, b_hi, b_lo).   W_lo term DROPPED (f16-exact h, f16 W).
// B: 16 rows;  cols [0,64) h_hi, [64,128) h_lo, [128..131] (x,x,1,1); double-buffered
constexpr int ASTR     = 304;                     // bytes per row
constexpr int OFF_B    = 256 * ASTR;              // 77824
constexpr int BBUF     = NR * ASTR;               // 4864
constexpr int OFF_HS   = OFF_B + 2 * BBUF;        // 87552
constexpr int DYN_SMEM = OFF_HS + NR * 257 * 4;   // 103984

// ======================= kernel =======================
// 256 threads = 8 warps, 2 CTAs/SM. Warp w owns gate-rows [32w, 32w+32) ==
// units 8w..8w+7 (row order: j 0-7 = gate i, 8-15 = f, 16-23 = g, 24-31 = o).
// Thread T holds (i,f) of unit u=8w+T/4 in M-tile 2w accum rows (T/4, T/4+8)
// and (g,o) in M-tile 2w+1 -> all 4 gates in-register, zero epilogue exchange.
// Per warp-step: 9 kt x 2mt x 2nt = 36 HMMA (was 52).
__global__ __launch_bounds__(256, 2)
void trend_lstm_mma(const float* __restrict__ time_,
                    const int*   __restrict__ length_,
                    const float* __restrict__ predict_time_,
                    const float* __restrict__ W_ih,
                    const float* __restrict__ W_hh,
                    const float* __restrict__ b_ih,
                    const float* __restrict__ b_hh,
                    float* __restrict__ out)
{
    extern __shared__ char sm[];
    float* hist = reinterpret_cast<float*>(sm + OFF_HS);    // [16][257]

    const int tid  = threadIdx.x;
    const int wid  = tid >> 5;
    const int lane = tid & 31;
    const int row0 = blockIdx.x * NR;
    const u32 Ab   = smem_u32(sm);
    const u32 Bb   = Ab + OFF_B;

    // ---- zero all SMEM ----
    for (int i = tid; i < DYN_SMEM / 4; i += 256)
        reinterpret_cast<u32*>(sm)[i] = 0u;
    __syncthreads();

    // ---- histogram (exact reference float math): 16 threads per batch row ----
    {
        const int r = tid & 15, sub = tid >> 4;
        const float pt  = predict_time_[row0 + r];
        const int   len = length_[row0 + r];
        const float* tr = time_ + (size_t)(row0 + r) * S_LEN;
        for (int s = sub; s < len; s += 16) {
            int pos = (int)((pt - tr[s]) * 0.25f);      // trunc toward 0, == /4
            if (pos >= 0 && pos < BINS)
                atomicAdd(&hist[r * 257 + (BINS - 1 - pos)], 1.0f);
        }
    }

    // ---- build A tile (f16 W_hh, reordered rows) ----
    for (int idx = tid; idx < 256 * 64; idx += 256) {
        int L = idx >> 6, k = idx & 63;
        int lw = L >> 5, j = L & 31;
        int unit = 8 * lw + (j & 7), gate = j >> 3;      // i,f,g,o order
        float wv = W_hh[(size_t)(gate * 64 + unit) * 64 + k];
        reinterpret_cast<__half*>(sm + L * ASTR)[k] = __float2half_rn(wv);
    }
    {   // epilogue chunk: x*W_ih + bias folded into K (hi/lo exact splits)
        int L = tid, lw = L >> 5, j = L & 31;
        int unit = 8 * lw + (j & 7), gate = j >> 3;
        float wi = W_ih[gate * 64 + unit];
        float bb = b_ih[gate * 64 + unit] + b_hh[gate * 64 + unit];
        __half wh = __float2half_rn(wi), wl = __float2half_rn(wi - __half2float(wh));
        __half bh = __float2half_rn(bb), bl = __float2half_rn(bb - __half2float(bh));
        __half* Arow = reinterpret_cast<__half*>(sm + L * ASTR);
        Arow[128] = wh; Arow[129] = wl; Arow[130] = bh; Arow[131] = bl;
    }
    if (tid < NR) {     // B constants: (1,1) at cols 130,131 in BOTH buffers
        sts32(Bb + tid * ASTR + 260, 0x3C003C00u);
        sts32(Bb + BBUF + tid * ASTR + 260, 0x3C003C00u);
    }
    __syncthreads();

    if (tid < NR) {     // x(0) into buffer 0 (h0 = 0 already)
        u16 xh = __half_as_ushort(__float2half_rn(hist[tid * 257]));
        sts32(Bb + tid * ASTR + 256, (u32)xh | ((u32)xh << 16));
    }

    // ---- load static A fragments into registers (once) ----
    const int m  = lane >> 3, lr = lane & 7;
    u32 Ahi[4][2][4], Aep[2][4];
#pragma unroll
    for (int mt = 0; mt < 2; mt++) {
        int arow = 32 * wid + 16 * mt + 8 * (m & 1) + lr;
        u32 ab   = Ab + arow * ASTR + 16 * (m >> 1);
#pragma unroll
        for (int kt = 0; kt < 4; kt++) ldsm4(Ahi[kt][mt], ab + 32 * kt);
        ldsm4(Aep[mt], ab + 256);
    }

    const int u = 8 * wid + (lane >> 2);     // owned unit
    // B LDSM: one x4 per kt covers all 16 batch rows x 16 k
    const u32 bfa = Bb + (8 * (m >> 1) + lr) * ASTR + 16 * (m & 1);
    float c_st[4], hl[4];
#pragma unroll
    for (int i = 0; i < 4; i++) c_st[i] = 0.0f;

    for (int t = 0; t < BINS; t++) {
        __syncthreads();                     // prev-step h writes visible
        const u32 bcur = bfa + (t & 1) * BBUF;
        const u32 Bnxt = Bb + ((t & 1) ^ 1) * BBUF;

        float acc[2][2][4];
#pragma unroll
        for (int mt = 0; mt < 2; mt++)
#pragma unroll
            for (int nt = 0; nt < 2; nt++)
#pragma unroll
                for (int e = 0; e < 4; e++) acc[mt][nt][e] = 0.0f;

#pragma unroll
        for (int kt = 0; kt < 9; kt++) {
            u32 br[4];                        // frags for nt0 (n0-7) + nt1 (n8-15)
            ldsm4(br, bcur + 32 * kt);
            const u32* Af0 = (kt < 4) ? Ahi[kt][0] : (kt < 8) ? Ahi[kt - 4][0] : Aep[0];
            const u32* Af1 = (kt < 4) ? Ahi[kt][1] : (kt < 8) ? Ahi[kt - 4][1] : Aep[1];
            mma16816(acc[0][0], Af0, &br[0]);
            mma16816(acc[0][1], Af0, &br[2]);
            mma16816(acc[1][0], Af1, &br[0]);
            mma16816(acc[1][1], Af1, &br[2]);
        }

        // ---- activation: all 4 gates of unit u live in THIS thread's accums ----
#pragma unroll
        for (int nt = 0; nt < 2; nt++)
#pragma unroll
            for (int d = 0; d < 2; d++) {
                float gi = acc[0][nt][d],     gf = acc[0][nt][2 + d];
                float gg = acc[1][nt][d],     go = acc[1][nt][2 + d];
                int   ci = 2 * nt + d;
                float cc = hsig(gf) * c_st[ci] + hsig(gi) * htanh(gg);
                c_st[ci] = cc;
                float hv = hsig(go) * htanh(cc);
                hl[ci]   = hv;
                int cb = 8 * nt + 2 * (lane & 3) + d;     // local batch col 0-15
                __half hh = __float2half_rn(hv);
                __half lo = __float2half_rn(hv - __half2float(hh));
                u32 wa = Bnxt + cb * ASTR + 2 * u;
                sts16(wa,       __half_as_ushort(hh));    // h_hi
                sts16(wa + 128, __half_as_ushort(lo));    // h_lo (exact h kept)
            }
        if (tid < NR) {                        // x(t+1)
            u16 xh = __half_as_ushort(__float2half_rn(hist[tid * 257 + t + 1]));
            sts32(Bnxt + tid * ASTR + 256, (u32)xh | ((u32)xh << 16));
        }
    }

#pragma unroll
    for (int nt = 0; nt < 2; nt++)
#pragma unroll
        for (int d = 0; d < 2; d++) {
            int cb = 8 * nt + 2 * (lane & 3) + d;
            out[(size_t)(row0 + cb) * 64 + u] = hl[2 * nt + d];
        }
}

extern "C" void kernel_launch(void* const* d_in, const int* in_sizes, int n_in,
                              void* d_out, int out_size)
{
    const float* time_  = (const float*)d_in[0];   // [4096, 200]
    const int*   length = (const int*)  d_in[1];   // [4096]
    const float* ptime  = (const float*)d_in[2];   // [4096]
    const float* W_ih   = (const float*)d_in[3];   // [256, 1]
    const float* W_hh   = (const float*)d_in[4];   // [256, 64]
    const float* b_ih   = (const float*)d_in[5];   // [256]
    const float* b_hh   = (const float*)d_in[6];   // [256]
    float* out = (float*)d_out;                    // [4096, 64]

    cudaFuncSetAttribute(trend_lstm_mma,
                         cudaFuncAttributeMaxDynamicSharedMemorySize, DYN_SMEM);
    const int B = in_sizes[1];                     // 4096
    trend_lstm_mma<<<B / NR, 256, DYN_SMEM>>>(time_, length, ptime,
                                              W_ih, W_hh, b_ih, b_hh, out);
}

// round 16
// speedup vs baseline: 4.6629x; 1.4628x over previous
#include <cuda_runtime.h>
#include <cuda_fp16.h>

typedef unsigned int   u32;
typedef unsigned short u16;

// ======================= warp-MMA helpers (compute_80+, safe on compute_103) ==
__device__ __forceinline__ u32 smem_u32(const void* p) {
    u32 a;
    asm("{ .reg .u64 t; cvta.to.shared.u64 t, %1; cvt.u32.u64 %0, t; }"
        : "=r"(a) : "l"(p));
    return a;
}
__device__ __forceinline__ void ldsm4(u32* r, u32 addr) {
    asm volatile("ldmatrix.sync.aligned.m8n8.x4.shared.b16 {%0,%1,%2,%3}, [%4];"
                 : "=r"(r[0]), "=r"(r[1]), "=r"(r[2]), "=r"(r[3]) : "r"(addr));
}
__device__ __forceinline__ void mma16816(float* c, const u32* a, const u32* b) {
    asm volatile(
        "mma.sync.aligned.m16n8k16.row.col.f32.f16.f16.f32 "
        "{%0,%1,%2,%3}, {%4,%5,%6,%7}, {%8,%9}, {%0,%1,%2,%3};"
        : "+f"(c[0]), "+f"(c[1]), "+f"(c[2]), "+f"(c[3])
        : "r"(a[0]), "r"(a[1]), "r"(a[2]), "r"(a[3]), "r"(b[0]), "r"(b[1]));
}
__device__ __forceinline__ void sts16(u32 addr, u16 v) {
    asm volatile("st.shared.u16 [%0], %1;" :: "r"(addr), "h"(v) : "memory");
}
__device__ __forceinline__ float htanh(float x) {
    float y; asm("tanh.approx.f32 %0, %1;" : "=f"(y) : "f"(x)); return y;
}
__device__ __forceinline__ float hsig(float x) { return fmaf(0.5f, htanh(0.5f * x), 0.5f); }

// ======================= constants =======================
constexpr int S_LEN = 200, BINS = 256, NR = 16;   // 16 batch rows/CTA, 2 CTAs/SM
// f16 tiles, row stride 176 bytes (mod 128 = 48 -> 8-row LDSM conflict-free)
// A: 256 rows x 64 f16 (W_hi only).  B: 16 rows x 64 f16 (h as single f16),
// double-buffered.  Epilogue (x*W_ih + bias) is scalar fp32 at activation time.
constexpr int ASTR     = 176;                     // bytes per row
constexpr int OFF_B    = 256 * ASTR;              // 45056
constexpr int BBUF     = NR * ASTR;               // 2816
constexpr int OFF_HS   = OFF_B + 2 * BBUF;        // 50688
constexpr int DYN_SMEM = OFF_HS + NR * 257 * 4;   // 67136

// ======================= kernel =======================
// 256 threads = 8 warps. Warp w owns gate-rows [32w, 32w+32) == units 8w..8w+7
// (row order: j 0-7 = gate i, 8-15 = f, 16-23 = g, 24-31 = o).
// Thread T holds (i,f) of unit u=8w+T/4 in M-tile 2w accum rows (T/4, T/4+8)
// and (g,o) in M-tile 2w+1 -> all 4 gates in-register, zero epilogue exchange.
// Per warp-step: 4 kt x 2mt x 2nt = 16 HMMA (was 36).
__global__ __launch_bounds__(256, 2)
void trend_lstm_mma(const float* __restrict__ time_,
                    const int*   __restrict__ length_,
                    const float* __restrict__ predict_time_,
                    const float* __restrict__ W_ih,
                    const float* __restrict__ W_hh,
                    const float* __restrict__ b_ih,
                    const float* __restrict__ b_hh,
                    float* __restrict__ out)
{
    extern __shared__ char sm[];
    float* hist = reinterpret_cast<float*>(sm + OFF_HS);    // [16][257]

    const int tid  = threadIdx.x;
    const int wid  = tid >> 5;
    const int lane = tid & 31;
    const int row0 = blockIdx.x * NR;
    const u32 Ab   = smem_u32(sm);
    const u32 Bb   = Ab + OFF_B;

    // ---- zero all SMEM (h0 = 0, hist = 0) ----
    for (int i = tid; i < DYN_SMEM / 4; i += 256)
        reinterpret_cast<u32*>(sm)[i] = 0u;
    __syncthreads();

    // ---- histogram (exact reference float math): 16 threads per batch row ----
    {
        const int r = tid & 15, sub = tid >> 4;
        const float pt  = predict_time_[row0 + r];
        const int   len = length_[row0 + r];
        const float* tr = time_ + (size_t)(row0 + r) * S_LEN;
        for (int s = sub; s < len; s += 16) {
            int pos = (int)((pt - tr[s]) * 0.25f);      // trunc toward 0, == /4
            if (pos >= 0 && pos < BINS)
                atomicAdd(&hist[r * 257 + (BINS - 1 - pos)], 1.0f);
        }
    }

    // ---- build A tile (f16 W_hh, reordered rows) ----
    for (int idx = tid; idx < 256 * 64; idx += 256) {
        int L = idx >> 6, k = idx & 63;
        int lw = L >> 5, j = L & 31;
        int unit = 8 * lw + (j & 7), gate = j >> 3;      // i,f,g,o order
        float wv = W_hh[(size_t)(gate * 64 + unit) * 64 + k];
        reinterpret_cast<__half*>(sm + L * ASTR)[k] = __float2half_rn(wv);
    }
    __syncthreads();

    // ---- per-thread epilogue constants (unit u, fp32-exact path) ----
    const int u = 8 * wid + (lane >> 2);                 // owned unit
    float wih[4], bias[4];
#pragma unroll
    for (int g = 0; g < 4; g++) {
        wih[g]  = W_ih[g * 64 + u];
        bias[g] = b_ih[g * 64 + u] + b_hh[g * 64 + u];
    }

    // ---- load static A fragments into registers (once) ----
    const int m  = lane >> 3, lr = lane & 7;
    u32 Ahi[4][2][4];
#pragma unroll
    for (int mt = 0; mt < 2; mt++) {
        int arow = 32 * wid + 16 * mt + 8 * (m & 1) + lr;
        u32 ab   = Ab + arow * ASTR + 16 * (m >> 1);
#pragma unroll
        for (int kt = 0; kt < 4; kt++) ldsm4(Ahi[kt][mt], ab + 32 * kt);
    }

    // B LDSM: one x4 per kt covers all 16 batch rows x 16 k
    const u32 bfa = Bb + (8 * (m >> 1) + lr) * ASTR + 16 * (m & 1);
    float c_st[4], hl[4];
#pragma unroll
    for (int i = 0; i < 4; i++) c_st[i] = 0.0f;

    for (int t = 0; t < BINS; t++) {
        __syncthreads();                     // prev-step h writes visible
        const u32 bcur = bfa + (t & 1) * BBUF;
        const u32 Bnxt = Bb + ((t & 1) ^ 1) * BBUF;

        float acc[2][2][4];
#pragma unroll
        for (int mt = 0; mt < 2; mt++)
#pragma unroll
            for (int nt = 0; nt < 2; nt++)
#pragma unroll
                for (int e = 0; e < 4; e++) acc[mt][nt][e] = 0.0f;

#pragma unroll
        for (int kt = 0; kt < 4; kt++) {
            u32 br[4];                        // frags for nt0 (n0-7) + nt1 (n8-15)
            ldsm4(br, bcur + 32 * kt);
            mma16816(acc[0][0], Ahi[kt][0], &br[0]);
            mma16816(acc[0][1], Ahi[kt][0], &br[2]);
            mma16816(acc[1][0], Ahi[kt][1], &br[0]);
            mma16816(acc[1][1], Ahi[kt][1], &br[2]);
        }

        // ---- activation: all 4 gates of unit u in THIS thread's accums;
        //      x*W_ih + bias applied in exact fp32 here ----
#pragma unroll
        for (int nt = 0; nt < 2; nt++)
#pragma unroll
            for (int d = 0; d < 2; d++) {
                int   cb = 8 * nt + 2 * (lane & 3) + d;   // local batch col 0-15
                float x  = hist[cb * 257 + t];            // broadcast LDS
                float gi = fmaf(x, wih[0], acc[0][nt][d]     + bias[0]);
                float gf = fmaf(x, wih[1], acc[0][nt][2 + d] + bias[1]);
                float gg = fmaf(x, wih[2], acc[1][nt][d]     + bias[2]);
                float go = fmaf(x, wih[3], acc[1][nt][2 + d] + bias[3]);
                int   ci = 2 * nt + d;
                float cc = hsig(gf) * c_st[ci] + hsig(gi) * htanh(gg);
                c_st[ci] = cc;
                float hv = hsig(go) * htanh(cc);
                hl[ci]   = hv;
                sts16(Bnxt + cb * ASTR + 2 * u,
                      __half_as_ushort(__float2half_rn(hv)));
            }
    }

#pragma unroll
    for (int nt = 0; nt < 2; nt++)
#pragma unroll
        for (int d = 0; d < 2; d++) {
            int cb = 8 * nt + 2 * (lane & 3) + d;
            out[(size_t)(row0 + cb) * 64 + u] = hl[2 * nt + d];
        }
}

extern "C" void kernel_launch(void* const* d_in, const int* in_sizes, int n_in,
                              void* d_out, int out_size)
{
    const float* time_  = (const float*)d_in[0];   // [4096, 200]
    const int*   length = (const int*)  d_in[1];   // [4096]
    const float* ptime  = (const float*)d_in[2];   // [4096]
    const float* W_ih   = (const float*)d_in[3];   // [256, 1]
    const float* W_hh   = (const float*)d_in[4];   // [256, 64]
    const float* b_ih   = (const float*)d_in[5];   // [256]
    const float* b_hh   = (const float*)d_in[6];   // [256]
    float* out = (float*)d_out;                    // [4096, 64]

    cudaFuncSetAttribute(trend_lstm_mma,
                         cudaFuncAttributeMaxDynamicSharedMemorySize, DYN_SMEM);
    const int B = in_sizes[1];                     // 4096
    trend_lstm_mma<<<B / NR, 256, DYN_SMEM>>>(time_, length, ptime,
                                              W_ih, W_hh, b_ih, b_hh, out);
}

// round 17
// speedup vs baseline: 5.1896x; 1.1129x over previous
#include <cuda_runtime.h>
#include <cuda_fp16.h>

typedef unsigned int   u32;
typedef unsigned short u16;

// ======================= warp-MMA helpers (compute_80+, safe on compute_103) ==
__device__ __forceinline__ u32 smem_u32(const void* p) {
    u32 a;
    asm("{ .reg .u64 t; cvta.to.shared.u64 t, %1; cvt.u32.u64 %0, t; }"
        : "=r"(a) : "l"(p));
    return a;
}
__device__ __forceinline__ void ldsm4(u32* r, u32 addr) {
    asm volatile("ldmatrix.sync.aligned.m8n8.x4.shared.b16 {%0,%1,%2,%3}, [%4];"
                 : "=r"(r[0]), "=r"(r[1]), "=r"(r[2]), "=r"(r[3]) : "r"(addr));
}
__device__ __forceinline__ void mma16816(float* c, const u32* a, const u32* b) {
    asm volatile(
        "mma.sync.aligned.m16n8k16.row.col.f32.f16.f16.f32 "
        "{%0,%1,%2,%3}, {%4,%5,%6,%7}, {%8,%9}, {%0,%1,%2,%3};"
        : "+f"(c[0]), "+f"(c[1]), "+f"(c[2]), "+f"(c[3])
        : "r"(a[0]), "r"(a[1]), "r"(a[2]), "r"(a[3]), "r"(b[0]), "r"(b[1]));
}
__device__ __forceinline__ void sts16(u32 addr, u16 v) {
    asm volatile("st.shared.u16 [%0], %1;" :: "r"(addr), "h"(v) : "memory");
}
__device__ __forceinline__ float htanh(float x) {
    float y; asm("tanh.approx.f32 %0, %1;" : "=f"(y) : "f"(x)); return y;
}
__device__ __forceinline__ float hsig(float x) { return fmaf(0.5f, htanh(0.5f * x), 0.5f); }

// ======================= constants =======================
constexpr int S_LEN = 200, BINS = 256, NR = 8;    // 8 batch rows/CTA -> 4 CTAs/SM
// f16 tiles, row stride 176 bytes (mod 128 = 48 -> 8-row LDSM conflict-free)
// A: 256 rows x 64 f16 (W_hi).  B: 8 rows x 64 f16 (h as f16), double-buffered.
// Epilogue (x*W_ih + bias) stays scalar fp32 at activation time.
constexpr int ASTR     = 176;                     // bytes per row
constexpr int OFF_B    = 256 * ASTR;              // 45056
constexpr int BBUF     = NR * ASTR;               // 1408
constexpr int OFF_HS   = OFF_B + 2 * BBUF;        // 47872
constexpr int DYN_SMEM = OFF_HS + NR * 257 * 4;   // 56096  (x4 CTAs = 224 KB)

// ======================= kernel =======================
// 256 threads = 8 warps, 4 CTAs/SM. Warp w owns gate-rows [32w,32w+32) ==
// units 8w..8w+7 (row order: j 0-7 = gate i, 8-15 = f, 16-23 = g, 24-31 = o).
// Thread T holds (i,f) of unit u=8w+T/4 in M-tile 2w accum rows (T/4, T/4+8)
// and (g,o) in M-tile 2w+1 -> all 4 gates in-register, zero epilogue exchange.
// Per warp-step: 4 kt x 2 mt x 1 nt = 8 HMMA, 2 B-LDSM, 2 elements' MUFU.
__global__ __launch_bounds__(256, 4)
void trend_lstm_mma(const float* __restrict__ time_,
                    const int*   __restrict__ length_,
                    const float* __restrict__ predict_time_,
                    const float* __restrict__ W_ih,
                    const float* __restrict__ W_hh,
                    const float* __restrict__ b_ih,
                    const float* __restrict__ b_hh,
                    float* __restrict__ out)
{
    extern __shared__ char sm[];
    float* hist = reinterpret_cast<float*>(sm + OFF_HS);    // [8][257]

    const int tid  = threadIdx.x;
    const int wid  = tid >> 5;
    const int lane = tid & 31;
    const int row0 = blockIdx.x * NR;
    const u32 Ab   = smem_u32(sm);
    const u32 Bb   = Ab + OFF_B;

    // ---- zero all SMEM (h0 = 0, hist = 0) ----
    for (int i = tid; i < DYN_SMEM / 4; i += 256)
        reinterpret_cast<u32*>(sm)[i] = 0u;
    __syncthreads();

    // ---- histogram (exact reference float math): 32 threads per batch row ----
    {
        const int r = tid & 7, sub = tid >> 3;
        const float pt  = predict_time_[row0 + r];
        const int   len = length_[row0 + r];
        const float* tr = time_ + (size_t)(row0 + r) * S_LEN;
        for (int s = sub; s < len; s += 32) {
            int pos = (int)((pt - tr[s]) * 0.25f);      // trunc toward 0, == /4
            if (pos >= 0 && pos < BINS)
                atomicAdd(&hist[r * 257 + (BINS - 1 - pos)], 1.0f);
        }
    }

    // ---- build A tile (f16 W_hh, reordered rows) ----
    for (int idx = tid; idx < 256 * 64; idx += 256) {
        int L = idx >> 6, k = idx & 63;
        int lw = L >> 5, j = L & 31;
        int unit = 8 * lw + (j & 7), gate = j >> 3;      // i,f,g,o order
        float wv = W_hh[(size_t)(gate * 64 + unit) * 64 + k];
        reinterpret_cast<__half*>(sm + L * ASTR)[k] = __float2half_rn(wv);
    }
    __syncthreads();

    // ---- per-thread epilogue constants (unit u, fp32-exact path) ----
    const int u = 8 * wid + (lane >> 2);                 // owned unit
    float wih[4], bias[4];
#pragma unroll
    for (int g = 0; g < 4; g++) {
        wih[g]  = W_ih[g * 64 + u];
        bias[g] = b_ih[g * 64 + u] + b_hh[g * 64 + u];
    }

    // ---- load static A fragments into registers (once) ----
    const int m  = lane >> 3, lr = lane & 7;
    u32 Ahi[4][2][4];
#pragma unroll
    for (int mt = 0; mt < 2; mt++) {
        int arow = 32 * wid + 16 * mt + 8 * (m & 1) + lr;
        u32 ab   = Ab + arow * ASTR + 16 * (m >> 1);
#pragma unroll
        for (int kt = 0; kt < 4; kt++) ldsm4(Ahi[kt][mt], ab + 32 * kt);
    }

    // B LDSM: lane -> tile m (k-block), row lr; one x4 covers 8 rows x 32 k
    const u32 bfa = Bb + lr * ASTR + 16 * m;
    const int cb  = 2 * (lane & 3);          // local batch cols cb, cb+1
    float c_st[2], hl[2];
    c_st[0] = c_st[1] = 0.0f;

    for (int t = 0; t < BINS; t++) {
        __syncthreads();                     // prev-step h writes visible
        const u32 bcur = bfa + (t & 1) * BBUF;
        const u32 Bnxt = Bb + ((t & 1) ^ 1) * BBUF;

        float acc[2][4];
#pragma unroll
        for (int mt = 0; mt < 2; mt++)
#pragma unroll
            for (int e = 0; e < 4; e++) acc[mt][e] = 0.0f;

        u32 br0[4], br1[4];                  // k0-31, k32-63
        ldsm4(br0, bcur);
        ldsm4(br1, bcur + 64);
        mma16816(acc[0], Ahi[0][0], &br0[0]);
        mma16816(acc[1], Ahi[0][1], &br0[0]);
        mma16816(acc[0], Ahi[1][0], &br0[2]);
        mma16816(acc[1], Ahi[1][1], &br0[2]);
        mma16816(acc[0], Ahi[2][0], &br1[0]);
        mma16816(acc[1], Ahi[2][1], &br1[0]);
        mma16816(acc[0], Ahi[3][0], &br1[2]);
        mma16816(acc[1], Ahi[3][1], &br1[2]);

        // ---- activation: all 4 gates of unit u in THIS thread's accums;
        //      x*W_ih + bias applied in exact fp32 here ----
#pragma unroll
        for (int d = 0; d < 2; d++) {
            int   cbl = cb + d;                        // local batch col 0-7
            float x   = hist[cbl * 257 + t];           // LDS
            float gi  = fmaf(x, wih[0], acc[0][d]     + bias[0]);
            float gf  = fmaf(x, wih[1], acc[0][2 + d] + bias[1]);
            float gg  = fmaf(x, wih[2], acc[1][d]     + bias[2]);
            float go  = fmaf(x, wih[3], acc[1][2 + d] + bias[3]);
            float cc  = hsig(gf) * c_st[d] + hsig(gi) * htanh(gg);
            c_st[d]   = cc;
            float hv  = hsig(go) * htanh(cc);
            hl[d]     = hv;
            sts16(Bnxt + cbl * ASTR + 2 * u,
                  __half_as_ushort(__float2half_rn(hv)));
        }
    }

#pragma unroll
    for (int d = 0; d < 2; d++)
        out[(size_t)(row0 + cb + d) * 64 + u] = hl[d];
}

extern "C" void kernel_launch(void* const* d_in, const int* in_sizes, int n_in,
                              void* d_out, int out_size)
{
    const float* time_  = (const float*)d_in[0];   // [4096, 200]
    const int*   length = (const int*)  d_in[1];   // [4096]
    const float* ptime  = (const float*)d_in[2];   // [4096]
    const float* W_ih   = (const float*)d_in[3];   // [256, 1]
    const float* W_hh   = (const float*)d_in[4];   // [256, 64]
    const float* b_ih   = (const float*)d_in[5];   // [256]
    const float* b_hh   = (const float*)d_in[6];   // [256]
    float* out = (float*)d_out;                    // [4096, 64]

    cudaFuncSetAttribute(trend_lstm_mma,
                         cudaFuncAttributeMaxDynamicSharedMemorySize, DYN_SMEM);
    const int B = in_sizes[1];                     // 4096
    trend_lstm_mma<<<B / NR, 256, DYN_SMEM>>>(time_, length, ptime,
                                              W_ih, W_hh, b_ih, b_hh, out);
}